// round 5
// baseline (speedup 1.0000x reference)
#include <cuda_runtime.h>

// Problem constants (fixed shapes from reference)
#define BT_   4096   // B*T
#define L_    16
#define E_    256
#define H_    512
#define G4_   2048   // 4*H
#define VOC_  256

// Scratch in __device__ globals (no allocation allowed in kernel_launch)
__device__ float g_XG[VOC_ * G4_];     // 2 MB  : per-vocab input-gate precompute (+bias)
__device__ float g_gates[BT_ * G4_];   // 32 MB : per-step gate pre-activations
__device__ float g_c[BT_ * H_];        // 8 MB  : cell state

// ---------------------------------------------------------------------------
// Zero h (lives in d_out) and c
// ---------------------------------------------------------------------------
__global__ void init_kernel(float* __restrict__ h) {
    int i = blockIdx.x * blockDim.x + threadIdx.x;
    if (i < BT_ * H_) {
        h[i] = 0.f;
        g_c[i] = 0.f;
    }
}

// ---------------------------------------------------------------------------
// XG[v][n] = sum_e emb[v][e] * W_ih[n][e] + b_ih[n] + b_hh[n]
// 256 x 2048 x 256 GEMM — tiny one-time cost, simple 16x16 tiles.
// ---------------------------------------------------------------------------
__global__ void xg_kernel(const float* __restrict__ emb,
                          const float* __restrict__ W_ih,
                          const float* __restrict__ b_ih,
                          const float* __restrict__ b_hh) {
    __shared__ float Es[16][16];
    __shared__ float Ws[16][17];
    int tx = threadIdx.x, ty = threadIdx.y;
    int n = blockIdx.x * 16 + tx;
    int v = blockIdx.y * 16 + ty;
    float acc = 0.f;
    for (int k0 = 0; k0 < E_; k0 += 16) {
        Es[ty][tx] = emb[v * E_ + k0 + tx];
        Ws[ty][tx] = W_ih[(blockIdx.x * 16 + ty) * E_ + k0 + tx];
        __syncthreads();
#pragma unroll
        for (int k = 0; k < 16; k++) acc += Es[ty][k] * Ws[tx][k];
        __syncthreads();
    }
    g_XG[v * G4_ + n] = acc + b_ih[n] + b_hh[n];
}

// ---------------------------------------------------------------------------
// Recurrent GEMM: gates[m][n] = sum_k h[m][k] * W_hh[n][k] + XG[seq[m][t]][n]
// M=4096, N=2048, K=512. 128x128 block tile, BK=8, 256 threads, 8x8 microtile.
// Both A (h) and B (W_hh) are K-contiguous row-major -> coalesced float4 loads,
// transposed scatter into k-major smem tiles.
// ---------------------------------------------------------------------------
__global__ void __launch_bounds__(256)
gemm_kernel(const float* __restrict__ h,
            const float* __restrict__ W,
            const int* __restrict__ seq,
            int t) {
    __shared__ float As[8][128];
    __shared__ float Bs[8][128];

    const int tid  = threadIdx.x;
    const int bm   = blockIdx.y * 128;
    const int bn   = blockIdx.x * 128;
    const int lrow = tid >> 1;          // 0..127
    const int lk4  = (tid & 1) << 2;    // 0 or 4
    const float* Ap = h + (bm + lrow) * H_ + lk4;
    const float* Bp = W + (bn + lrow) * H_ + lk4;
    const int tx = tid & 15;            // N microtile: cols tx*8..tx*8+7
    const int ty = tid >> 4;            // M microtile: rows ty*8..ty*8+7

    float acc[8][8];
#pragma unroll
    for (int i = 0; i < 8; i++)
#pragma unroll
        for (int j = 0; j < 8; j++) acc[i][j] = 0.f;

    for (int k0 = 0; k0 < H_; k0 += 8) {
        float4 a = *(const float4*)(Ap + k0);
        float4 b = *(const float4*)(Bp + k0);
        As[lk4 + 0][lrow] = a.x; As[lk4 + 1][lrow] = a.y;
        As[lk4 + 2][lrow] = a.z; As[lk4 + 3][lrow] = a.w;
        Bs[lk4 + 0][lrow] = b.x; Bs[lk4 + 1][lrow] = b.y;
        Bs[lk4 + 2][lrow] = b.z; Bs[lk4 + 3][lrow] = b.w;
        __syncthreads();
#pragma unroll
        for (int k = 0; k < 8; k++) {
            float4 a0 = *(const float4*)&As[k][ty * 8];
            float4 a1 = *(const float4*)&As[k][ty * 8 + 4];
            float4 b0 = *(const float4*)&Bs[k][tx * 8];
            float4 b1 = *(const float4*)&Bs[k][tx * 8 + 4];
            float ar[8] = {a0.x, a0.y, a0.z, a0.w, a1.x, a1.y, a1.z, a1.w};
            float br[8] = {b0.x, b0.y, b0.z, b0.w, b1.x, b1.y, b1.z, b1.w};
#pragma unroll
            for (int i = 0; i < 8; i++)
#pragma unroll
                for (int j = 0; j < 8; j++)
                    acc[i][j] = fmaf(ar[i], br[j], acc[i][j]);
        }
        __syncthreads();
    }

    // Epilogue: add per-token input-projection row (XG lookup) and store gates.
#pragma unroll
    for (int i = 0; i < 8; i++) {
        int m  = bm + ty * 8 + i;
        int id = seq[m * L_ + t];  // char_seq_padded[m][t]
        const float4* xg = (const float4*)(g_XG + id * G4_ + bn + tx * 8);
        float4* gp = (float4*)(g_gates + m * G4_ + bn + tx * 8);
        float4 x0 = xg[0], x1 = xg[1];
        float4 o0 = make_float4(acc[i][0] + x0.x, acc[i][1] + x0.y,
                                acc[i][2] + x0.z, acc[i][3] + x0.w);
        float4 o1 = make_float4(acc[i][4] + x1.x, acc[i][5] + x1.y,
                                acc[i][6] + x1.z, acc[i][7] + x1.w);
        gp[0] = o0; gp[1] = o1;
    }
}

// ---------------------------------------------------------------------------
// LSTM cell pointwise + length mask (conditional update == mask blend)
// ---------------------------------------------------------------------------
__device__ __forceinline__ float sigmoidf_(float x) {
    return 1.f / (1.f + expf(-x));
}

__global__ void pointwise_kernel(const int* __restrict__ lens,
                                 float* __restrict__ h, int t) {
    int idx = blockIdx.x * blockDim.x + threadIdx.x;
    if (idx >= BT_ * H_) return;
    int m = idx >> 9;            // H_ = 512
    if (lens[m] <= t) return;    // past this sequence's length: keep h, c
    int j = idx & (H_ - 1);
    const float* gr = g_gates + m * G4_;
    float ig = sigmoidf_(gr[j]);
    float fg = sigmoidf_(gr[H_ + j]);
    float gg = tanhf(gr[2 * H_ + j]);
    float og = sigmoidf_(gr[3 * H_ + j]);
    float cn = fg * g_c[idx] + ig * gg;
    g_c[idx] = cn;
    h[idx] = og * tanhf(cn);
}

// ---------------------------------------------------------------------------
// Launch: init -> XG precompute -> 16 x (gemm, pointwise). Graph-capturable.
// ---------------------------------------------------------------------------
extern "C" void kernel_launch(void* const* d_in, const int* in_sizes, int n_in,
                              void* d_out, int out_size) {
    const int*   seq  = (const int*)d_in[0];     // [32,128,16] int32
    const int*   lens = (const int*)d_in[1];     // [32,128]    int32
    const float* emb  = (const float*)d_in[2];   // [256,256]
    const float* W_ih = (const float*)d_in[3];   // [2048,256]
    const float* W_hh = (const float*)d_in[4];   // [2048,512]
    const float* b_ih = (const float*)d_in[5];   // [2048]
    const float* b_hh = (const float*)d_in[6];   // [2048]
    float* h = (float*)d_out;                    // [4096,512] = final hidden state

    init_kernel<<<(BT_ * H_ + 255) / 256, 256>>>(h);

    dim3 xgrid(G4_ / 16, VOC_ / 16);
    xg_kernel<<<xgrid, dim3(16, 16)>>>(emb, W_ih, b_ih, b_hh);

    dim3 ggrid(G4_ / 128, BT_ / 128);   // (16, 32) = 512 CTAs
    for (int t = 0; t < L_; t++) {
        gemm_kernel<<<ggrid, 256>>>(h, W_hh, seq, t);
        pointwise_kernel<<<(BT_ * H_ + 255) / 256, 256>>>(lens, h, t);
    }
}

// round 9
// speedup vs baseline: 1.4540x; 1.4540x over previous
#include <cuda_runtime.h>
#include <cuda_bf16.h>
#include <mma.h>

using namespace nvcuda;

// Problem constants (fixed shapes from reference)
#define BT_   4096   // B*T
#define L_    16
#define E_    256
#define H_    512
#define G4_   2048   // 4*H
#define VOC_  256

// Scratch in __device__ globals (no allocation allowed in kernel_launch).
// NOTE: never pass these as kernel arguments from host code — taking the
// address of a __device__ symbol in host code yields the host shadow address,
// which on GB300 (ATS-coherent) is silently writable host memory. Reference
// them directly from device code only.
__device__ float          g_XG[VOC_ * G4_];      // 2 MB : per-vocab input proj (+bias)
__device__ float          g_gates[BT_ * G4_];    // 32 MB: recurrent-part gate preacts
__device__ float          g_c[BT_ * H_];         // 8 MB : cell state
__device__ __nv_bfloat16  g_hA[BT_ * 2 * H_];    // 8 MB : h split  [m][0:512)=hi [512:1024)=lo
__device__ __nv_bfloat16  g_WB[G4_ * 2 * H_];    // 8 MB : W_hh split, same hi/lo layout

__device__ __forceinline__ void split_bf16(float x, __nv_bfloat16& hi, __nv_bfloat16& lo) {
    hi = __float2bfloat16_rn(x);
    lo = __float2bfloat16_rn(x - __bfloat162float(hi));
}

// ---------------------------------------------------------------------------
// Zero h (d_out), c, and the bf16 split of h
// ---------------------------------------------------------------------------
__global__ void init_kernel(float* __restrict__ h) {
    int i = blockIdx.x * blockDim.x + threadIdx.x;
    if (i < BT_ * 2 * H_) {
        g_hA[i] = __float2bfloat16(0.f);
        if (i < BT_ * H_) { h[i] = 0.f; g_c[i] = 0.f; }
    }
}

// ---------------------------------------------------------------------------
// Split W_hh [2048][512] into bf16 hi/lo pairs [2048][1024]
// ---------------------------------------------------------------------------
__global__ void wsplit_kernel(const float* __restrict__ W) {
    int i = blockIdx.x * blockDim.x + threadIdx.x;
    if (i >= G4_ * H_) return;
    int r = i / H_, c = i % H_;
    __nv_bfloat16 hi, lo;
    split_bf16(W[i], hi, lo);
    g_WB[r * (2 * H_) + c]      = hi;
    g_WB[r * (2 * H_) + H_ + c] = lo;
}

// ---------------------------------------------------------------------------
// XG[v][n] = sum_e emb[v][e] * W_ih[n][e] + b_ih[n] + b_hh[n]   (fp32, exact)
// ---------------------------------------------------------------------------
__global__ void xg_kernel(const float* __restrict__ emb,
                          const float* __restrict__ W_ih,
                          const float* __restrict__ b_ih,
                          const float* __restrict__ b_hh) {
    __shared__ float Es[16][16];
    __shared__ float Ws[16][17];
    int tx = threadIdx.x, ty = threadIdx.y;
    int n = blockIdx.x * 16 + tx;
    int v = blockIdx.y * 16 + ty;
    float acc = 0.f;
    for (int k0 = 0; k0 < E_; k0 += 16) {
        Es[ty][tx] = emb[v * E_ + k0 + tx];
        Ws[ty][tx] = W_ih[(blockIdx.x * 16 + ty) * E_ + k0 + tx];
        __syncthreads();
#pragma unroll
        for (int k = 0; k < 16; k++) acc += Es[ty][k] * Ws[tx][k];
        __syncthreads();
    }
    g_XG[v * G4_ + n] = acc + b_ih[n] + b_hh[n];
}

// ---------------------------------------------------------------------------
// Recurrent GEMM on tensor cores, bf16x3 emulation of fp32:
//   gates[m][n] = sum_k h[m][k] * W[n][k]
//   = A_hi*B_hi + A_hi*B_lo + A_lo*B_hi   (fp32 accumulate, lo*lo negligible)
// M=4096, N=2048, K=512. 128x128 CTA tile, BK=32, 8 warps (64x32 warp tile).
// Writes g_gates directly (device symbol).
// ---------------------------------------------------------------------------
__global__ void __launch_bounds__(256)
gemm_bf16x3_kernel() {
    __shared__ __nv_bfloat16 As[128][40];   // [m][k], pad to 40 (mult of 8)
    __shared__ __nv_bfloat16 Bs[128][40];   // [n][k]

    const int tid = threadIdx.x;
    const int bn  = blockIdx.x * 128;
    const int bm  = blockIdx.y * 128;
    const int w   = tid >> 5;
    const int wm  = (w & 1) * 64;   // warp M offset within tile
    const int wn  = (w >> 1) * 32;  // warp N offset within tile

    // cooperative tile load mapping: each thread moves one 16-elem row segment
    const int lrow = tid >> 1;            // 0..127
    const int lcol = (tid & 1) * 16;      // 0 or 16

    wmma::fragment<wmma::accumulator, 16, 16, 16, float> acc[4][2];
#pragma unroll
    for (int i = 0; i < 4; i++)
#pragma unroll
        for (int j = 0; j < 2; j++) wmma::fill_fragment(acc[i][j], 0.f);

    const int aoff_tab[3] = {0, 0, H_};   // A: hi, hi, lo
    const int boff_tab[3] = {0, H_, 0};   // B: hi, lo, hi

#pragma unroll 1
    for (int p = 0; p < 3; p++) {
        const __nv_bfloat16* Ap = g_hA + (size_t)(bm + lrow) * (2 * H_) + aoff_tab[p] + lcol;
        const __nv_bfloat16* Bp = g_WB + (size_t)(bn + lrow) * (2 * H_) + boff_tab[p] + lcol;
#pragma unroll 1
        for (int k0 = 0; k0 < H_; k0 += 32) {
            // 16 bf16 = 32 bytes per thread per tile: two float4 moves
            float4 av0 = *(const float4*)(Ap + k0);
            float4 av1 = *(const float4*)(Ap + k0 + 8);
            float4 bv0 = *(const float4*)(Bp + k0);
            float4 bv1 = *(const float4*)(Bp + k0 + 8);
            *(float4*)&As[lrow][lcol]     = av0;
            *(float4*)&As[lrow][lcol + 8] = av1;
            *(float4*)&Bs[lrow][lcol]     = bv0;
            *(float4*)&Bs[lrow][lcol + 8] = bv1;
            __syncthreads();

#pragma unroll
            for (int ks = 0; ks < 2; ks++) {
                wmma::fragment<wmma::matrix_a, 16, 16, 16, __nv_bfloat16, wmma::row_major> af[4];
                wmma::fragment<wmma::matrix_b, 16, 16, 16, __nv_bfloat16, wmma::col_major> bf[2];
#pragma unroll
                for (int i = 0; i < 4; i++)
                    wmma::load_matrix_sync(af[i], &As[wm + i * 16][ks * 16], 40);
#pragma unroll
                for (int j = 0; j < 2; j++)
                    wmma::load_matrix_sync(bf[j], &Bs[wn + j * 16][ks * 16], 40);
#pragma unroll
                for (int i = 0; i < 4; i++)
#pragma unroll
                    for (int j = 0; j < 2; j++)
                        wmma::mma_sync(acc[i][j], af[i], bf[j], acc[i][j]);
            }
            __syncthreads();
        }
    }

#pragma unroll
    for (int i = 0; i < 4; i++)
#pragma unroll
        for (int j = 0; j < 2; j++)
            wmma::store_matrix_sync(g_gates + (size_t)(bm + wm + i * 16) * G4_ + bn + wn + j * 16,
                                    acc[i][j], G4_, wmma::mem_row_major);
}

// ---------------------------------------------------------------------------
// LSTM cell pointwise: gates = recurrent + XG[token] lookup; length mask;
// also emits the bf16 hi/lo split of h for the next step's GEMM.
// ---------------------------------------------------------------------------
__device__ __forceinline__ float sigmoidf_(float x) {
    return 1.f / (1.f + expf(-x));
}

__global__ void pointwise_kernel(const int* __restrict__ seq,
                                 const int* __restrict__ lens,
                                 float* __restrict__ h, int t) {
    int idx = blockIdx.x * blockDim.x + threadIdx.x;
    if (idx >= BT_ * H_) return;
    int m = idx >> 9;            // H_ = 512
    if (lens[m] <= t) return;    // frozen: keep h, c, hA
    int j = idx & (H_ - 1);
    int id = seq[m * L_ + t];
    const float* gr = g_gates + (size_t)m * G4_;
    const float* xr = g_XG + (size_t)id * G4_;
    float ig = sigmoidf_(gr[j]          + xr[j]);
    float fg = sigmoidf_(gr[H_ + j]     + xr[H_ + j]);
    float gg = tanhf(    gr[2 * H_ + j] + xr[2 * H_ + j]);
    float og = sigmoidf_(gr[3 * H_ + j] + xr[3 * H_ + j]);
    float cn = fg * g_c[idx] + ig * gg;
    g_c[idx] = cn;
    float hn = og * tanhf(cn);
    h[idx] = hn;
    __nv_bfloat16 hi, lo;
    split_bf16(hn, hi, lo);
    g_hA[(size_t)m * (2 * H_) + j]      = hi;
    g_hA[(size_t)m * (2 * H_) + H_ + j] = lo;
}

// ---------------------------------------------------------------------------
// Launch: init + splits + XG, then 16 x (tensor GEMM, pointwise).
// ---------------------------------------------------------------------------
extern "C" void kernel_launch(void* const* d_in, const int* in_sizes, int n_in,
                              void* d_out, int out_size) {
    const int*   seq  = (const int*)d_in[0];     // [32,128,16] int32
    const int*   lens = (const int*)d_in[1];     // [32,128]    int32
    const float* emb  = (const float*)d_in[2];   // [256,256]
    const float* W_ih = (const float*)d_in[3];   // [2048,256]
    const float* W_hh = (const float*)d_in[4];   // [2048,512]
    const float* b_ih = (const float*)d_in[5];   // [2048]
    const float* b_hh = (const float*)d_in[6];   // [2048]
    float* h = (float*)d_out;                    // [4096,512]

    init_kernel<<<(BT_ * 2 * H_ + 255) / 256, 256>>>(h);
    wsplit_kernel<<<(G4_ * H_ + 255) / 256, 256>>>(W_hh);

    dim3 xgrid(G4_ / 16, VOC_ / 16);
    xg_kernel<<<xgrid, dim3(16, 16)>>>(emb, W_ih, b_ih, b_hh);

    dim3 ggrid(G4_ / 128, BT_ / 128);   // (16, 32) = 512 CTAs
    for (int t = 0; t < L_; t++) {
        gemm_bf16x3_kernel<<<ggrid, 256>>>();
        pointwise_kernel<<<(BT_ * H_ + 255) / 256, 256>>>(seq, lens, h, t);
    }
}

// round 13
// speedup vs baseline: 1.4782x; 1.0167x over previous
#include <cuda_runtime.h>
#include <cuda_bf16.h>
#include <mma.h>
#include <cstdint>

using namespace nvcuda;

#define BT_   4096   // B*T
#define L_    16
#define E_    256
#define H_    512
#define G4_   2048   // 4*H
#define VOC_  256

// Device-global scratch. NEVER pass these as kernel args from host code
// (host shadow address + GB300 ATS = silent host-memory writes).
__device__ float          g_XG[VOC_ * G4_];          // 2 MB : permuted input proj (+bias)
__device__ float          g_c[BT_ * H_];             // 8 MB : cell state
__device__ __nv_bfloat16  g_hA[2][BT_ * 2 * H_];     // 16 MB: h split, double-buffered
                                                     //        [m][0:512)=hi [512:1024)=lo
__device__ __nv_bfloat16  g_WB[G4_ * 2 * H_];        // 8 MB : W_hh split (rows permuted 4u+q)

__device__ __forceinline__ uint32_t smem_u32(const void* p) {
    uint32_t a;
    asm("{ .reg .u64 t; cvta.to.shared.u64 t, %1; cvt.u32.u64 %0, t; }" : "=r"(a) : "l"(p));
    return a;
}
__device__ __forceinline__ void split_bf16(float x, __nv_bfloat16& hi, __nv_bfloat16& lo) {
    hi = __float2bfloat16_rn(x);
    lo = __float2bfloat16_rn(x - __bfloat162float(hi));
}
__device__ __forceinline__ float sigmoidf_(float x) { return 1.f / (1.f + expf(-x)); }

// ---------------------------------------------------------------------------
// init: zero h (d_out), c, both hA buffers
// ---------------------------------------------------------------------------
__global__ void init_kernel(float* __restrict__ h) {
    int i = blockIdx.x * blockDim.x + threadIdx.x;
    uint32_t* ha = (uint32_t*)&g_hA[0][0];
    if (i < 2 * BT_ * H_) ha[i] = 0u;
    if (i < BT_ * H_) { h[i] = 0.f; g_c[i] = 0.f; }
}

// ---------------------------------------------------------------------------
// W_hh split + gate permutation: row r (gate q=r>>9, unit u=r&511) -> 4u+q
// ---------------------------------------------------------------------------
__global__ void wsplit_kernel(const float* __restrict__ W) {
    int i = blockIdx.x * blockDim.x + threadIdx.x;
    if (i >= G4_ * H_) return;
    int r = i / H_, cc = i % H_;
    int pr = 4 * (r & 511) + (r >> 9);
    __nv_bfloat16 hi, lo;
    split_bf16(W[i], hi, lo);
    g_WB[(size_t)pr * (2 * H_) + cc]      = hi;
    g_WB[(size_t)pr * (2 * H_) + H_ + cc] = lo;
}

// ---------------------------------------------------------------------------
// XG[v][perm(n)] = emb[v]·W_ih[n] + b_ih[n] + b_hh[n]  (fp32 exact)
// ---------------------------------------------------------------------------
__global__ void xg_kernel(const float* __restrict__ emb,
                          const float* __restrict__ W_ih,
                          const float* __restrict__ b_ih,
                          const float* __restrict__ b_hh) {
    __shared__ float Es[16][16];
    __shared__ float Ws[16][17];
    int tx = threadIdx.x, ty = threadIdx.y;
    int n = blockIdx.x * 16 + tx;
    int v = blockIdx.y * 16 + ty;
    float acc = 0.f;
    for (int k0 = 0; k0 < E_; k0 += 16) {
        Es[ty][tx] = emb[v * E_ + k0 + tx];
        Ws[ty][tx] = W_ih[(blockIdx.x * 16 + ty) * E_ + k0 + tx];
        __syncthreads();
#pragma unroll
        for (int k = 0; k < 16; k++) acc += Es[ty][k] * Ws[tx][k];
        __syncthreads();
    }
    int pn = 4 * (n & 511) + (n >> 9);
    g_XG[v * G4_ + pn] = acc + b_ih[n] + b_hh[n];
}

// ---------------------------------------------------------------------------
// Fused step kernel: bf16x3 wmma GEMM (128x128 tile, BK=64, cp.async 2-stage
// pipeline) + LSTM cell epilogue (gate-permuted columns, smem staging).
// Grid (16, 32) = 512 CTAs, 256 threads, 2 CTAs/SM.
//
// SMEM map (74752 B dynamic):
//   [0,512)       ids[128]     (token id per CTA row)
//   [512,1024)    lens[128]
//   [1024,...)    pipeline: stage s: A[128][72] bf16 (18432B) + B[128][72]
//                 (2 stages * 36864B = 73728B)
//   epilogue reuses [1024,...): 8 warps * 9216B staging [64][36] fp32
// ---------------------------------------------------------------------------
#define LDMS  72        // smem row stride in bf16 elems (144B)
#define SM_IDS  0
#define SM_LENS 512
#define SM_PIPE 1024
#define STAGE_BYTES 36864
#define SMEM_TOTAL 74752

__global__ void __launch_bounds__(256, 2)
step_kernel(const int* __restrict__ seq, const int* __restrict__ lens,
            float* __restrict__ h, int t) {
    extern __shared__ char smem[];
    const uint32_t sb = smem_u32(smem);
    const int tid = threadIdx.x;
    const int bn  = blockIdx.x * 128;    // permuted gate-column tile
    const int bm  = blockIdx.y * 128;    // sequence rows
    const int rd  = t & 1, wr = rd ^ 1;

    int* ids_s  = (int*)(smem + SM_IDS);
    int* lens_s = (int*)(smem + SM_LENS);
    if (tid < 128) {
        ids_s[tid]  = seq[(bm + tid) * L_ + t];
        lens_s[tid] = lens[bm + tid];
    }

    const __nv_bfloat16* __restrict__ hA = g_hA[rd];
    const int aoff[3] = {0, 0, H_};      // passes: hi*hi, hi*lo, lo*hi
    const int boff[3] = {0, H_, 0};

    // cp.async mapping: thread -> (row = tid>>1, 64B half = tid&1), 4x16B each
    const int row  = tid >> 1;
    const int half = tid & 1;
    const __nv_bfloat16* Agbase = hA   + (size_t)(bm + row) * (2 * H_) + half * 32;
    const __nv_bfloat16* Bgbase = g_WB + (size_t)(bn + row) * (2 * H_) + half * 32;
    const uint32_t AsmBase = sb + SM_PIPE + row * 144 + half * 64;
    const uint32_t BsmBase = AsmBase + 18432;

#define ISSUE_CHUNK(c, s) do {                                                  \
    int _p = (c) >> 3, _k0 = ((c) & 7) * 64;                                    \
    const __nv_bfloat16* _ag = Agbase + aoff[_p] + _k0;                         \
    const __nv_bfloat16* _bg = Bgbase + boff[_p] + _k0;                         \
    uint32_t _as = AsmBase + (s) * STAGE_BYTES;                                 \
    uint32_t _bs = BsmBase + (s) * STAGE_BYTES;                                 \
    _Pragma("unroll")                                                           \
    for (int _v = 0; _v < 4; _v++) {                                            \
        asm volatile("cp.async.cg.shared.global [%0], [%1], 16;"                \
                     :: "r"(_as + _v * 16), "l"(_ag + _v * 8) : "memory");      \
        asm volatile("cp.async.cg.shared.global [%0], [%1], 16;"                \
                     :: "r"(_bs + _v * 16), "l"(_bg + _v * 8) : "memory");      \
    }                                                                           \
    asm volatile("cp.async.commit_group;" ::: "memory");                        \
} while (0)

    const int w  = tid >> 5;
    const int wm = (w & 1) * 64;         // warp M offset
    const int wn = (w >> 1) * 32;        // warp N offset

    wmma::fragment<wmma::accumulator, 16, 16, 16, float> acc[4][2];
#pragma unroll
    for (int i = 0; i < 4; i++)
#pragma unroll
        for (int j = 0; j < 2; j++) wmma::fill_fragment(acc[i][j], 0.f);

    ISSUE_CHUNK(0, 0);

#pragma unroll 1
    for (int c = 0; c < 24; c++) {       // 3 passes x 8 chunks (BK=64)
        if (c < 23) {
            ISSUE_CHUNK(c + 1, (c + 1) & 1);
            asm volatile("cp.async.wait_group 1;" ::: "memory");
        } else {
            asm volatile("cp.async.wait_group 0;" ::: "memory");
        }
        __syncthreads();
        const __nv_bfloat16* As =
            (const __nv_bfloat16*)(smem + SM_PIPE + (c & 1) * STAGE_BYTES);
        const __nv_bfloat16* Bs = As + 18432 / 2;   // bf16 elems
#pragma unroll
        for (int ks = 0; ks < 4; ks++) {
            wmma::fragment<wmma::matrix_a, 16, 16, 16, __nv_bfloat16, wmma::row_major> af[4];
            wmma::fragment<wmma::matrix_b, 16, 16, 16, __nv_bfloat16, wmma::col_major> bf[2];
#pragma unroll
            for (int i = 0; i < 4; i++)
                wmma::load_matrix_sync(af[i], As + (wm + i * 16) * LDMS + ks * 16, LDMS);
#pragma unroll
            for (int j = 0; j < 2; j++)
                wmma::load_matrix_sync(bf[j], Bs + (wn + j * 16) * LDMS + ks * 16, LDMS);
#pragma unroll
            for (int i = 0; i < 4; i++)
#pragma unroll
                for (int j = 0; j < 2; j++)
                    wmma::mma_sync(acc[i][j], af[i], bf[j], acc[i][j]);
        }
        __syncthreads();
    }
#undef ISSUE_CHUNK

    // ---- Epilogue: stage warp tile to smem, then LSTM cell ------------------
    float* stg = (float*)(smem + SM_PIPE + w * 9216);   // [64][36] fp32
#pragma unroll
    for (int i = 0; i < 4; i++)
#pragma unroll
        for (int j = 0; j < 2; j++)
            wmma::store_matrix_sync(stg + (i * 16) * 36 + j * 16, acc[i][j],
                                    36, wmma::mem_row_major);
    __syncwarp();

    const int lane  = tid & 31;
    const int u_loc = lane & 7;              // unit within warp's 8 units
    const int r0    = (lane >> 3) * 16;      // 16-row slab per lane
    const int hcol  = ((bn + wn) >> 2) + u_loc;
    __nv_bfloat16*       haw = g_hA[wr];
    const __nv_bfloat16* har = hA;

#pragma unroll 1
    for (int rr = 0; rr < 16; rr++) {
        const int r    = r0 + rr;            // row in warp tile
        const int mrow = wm + r;             // row in CTA tile
        const int m    = bm + mrow;
        const size_t hb = (size_t)m * (2 * H_) + hcol;
        if (lens_s[mrow] > t) {
            float4 g4 = *(float4*)(stg + r * 36 + u_loc * 4);
            const float* xr = g_XG + (size_t)ids_s[mrow] * G4_ + bn + wn + u_loc * 4;
            float4 x4 = *(const float4*)xr;
            float iv = sigmoidf_(g4.x + x4.x);
            float fv = sigmoidf_(g4.y + x4.y);
            float gv = tanhf(    g4.z + x4.z);
            float ov = sigmoidf_(g4.w + x4.w);
            const int ci = m * H_ + hcol;
            float cn = fv * g_c[ci] + iv * gv;
            g_c[ci] = cn;
            float hn = ov * tanhf(cn);
            h[ci] = hn;
            __nv_bfloat16 hi, lo;
            split_bf16(hn, hi, lo);
            haw[hb]      = hi;
            haw[hb + H_] = lo;
        } else {                              // frozen: carry split forward
            haw[hb]      = har[hb];
            haw[hb + H_] = har[hb + H_];
        }
    }
}

// ---------------------------------------------------------------------------
// Launch
// ---------------------------------------------------------------------------
extern "C" void kernel_launch(void* const* d_in, const int* in_sizes, int n_in,
                              void* d_out, int out_size) {
    const int*   seq  = (const int*)d_in[0];     // [32,128,16] int32
    const int*   lens = (const int*)d_in[1];     // [32,128]    int32
    const float* emb  = (const float*)d_in[2];   // [256,256]
    const float* W_ih = (const float*)d_in[3];   // [2048,256]
    const float* W_hh = (const float*)d_in[4];   // [2048,512]
    const float* b_ih = (const float*)d_in[5];   // [2048]
    const float* b_hh = (const float*)d_in[6];   // [2048]
    float* h = (float*)d_out;                    // [4096,512]

    cudaFuncSetAttribute(step_kernel, cudaFuncAttributeMaxDynamicSharedMemorySize,
                         SMEM_TOTAL);

    init_kernel<<<(2 * BT_ * H_ + 255) / 256, 256>>>(h);
    wsplit_kernel<<<(G4_ * H_ + 255) / 256, 256>>>(W_hh);
    xg_kernel<<<dim3(G4_ / 16, VOC_ / 16), dim3(16, 16)>>>(emb, W_ih, b_ih, b_hh);

    dim3 ggrid(G4_ / 128, BT_ / 128);            // (16, 32) = 512 CTAs
    for (int t = 0; t < L_; t++)
        step_kernel<<<ggrid, 256, SMEM_TOTAL>>>(seq, lens, h, t);
}

// round 17
// speedup vs baseline: 2.3821x; 1.6114x over previous
#include <cuda_runtime.h>
#include <cuda_bf16.h>
#include <mma.h>
#include <cstdint>

using namespace nvcuda;

#define BT_   4096   // B*T
#define L_    16
#define E_    256
#define H_    512
#define G4_   2048   // 4*H
#define VOC_  256

// Device-global scratch. NEVER pass these as kernel args from host code
// (host shadow address + GB300 ATS = silent host-memory writes).
__device__ float          g_XG[VOC_ * G4_];          // 2 MB : permuted input proj (+bias)
__device__ float          g_c[BT_ * H_];             // 8 MB : cell state (sorted space)
__device__ __nv_bfloat16  g_hA[2][BT_ * 2 * H_];     // 16 MB: h split (sorted space), dbl-buf
__device__ __nv_bfloat16  g_WB[G4_ * 2 * H_];        // 8 MB : W_hh split (rows permuted 4u+q)
// length-sort bookkeeping
__device__ int g_cnt[17];      // histogram of lens (1..16)
__device__ int g_off[17];      // bucket start offsets (desc length order); mutated by scatter
__device__ int g_Mt[18];       // M_t = #rows with len > t, t=0..16
__device__ int g_perm[BT_];    // sorted idx -> original row

__device__ __forceinline__ uint32_t smem_u32(const void* p) {
    uint32_t a;
    asm("{ .reg .u64 t; cvta.to.shared.u64 t, %1; cvt.u32.u64 %0, t; }" : "=r"(a) : "l"(p));
    return a;
}
__device__ __forceinline__ void split_bf16(float x, __nv_bfloat16& hi, __nv_bfloat16& lo) {
    hi = __float2bfloat16_rn(x);
    lo = __float2bfloat16_rn(x - __bfloat162float(hi));
}
__device__ __forceinline__ float sigmoidf_(float x) { return 1.f / (1.f + expf(-x)); }

// ---------------------------------------------------------------------------
// init: zero h (d_out), c, both hA buffers, histogram
// ---------------------------------------------------------------------------
__global__ void init_kernel(float* __restrict__ h) {
    int i = blockIdx.x * blockDim.x + threadIdx.x;
    uint32_t* ha = (uint32_t*)&g_hA[0][0];
    if (i < 2 * BT_ * H_) ha[i] = 0u;
    if (i < BT_ * H_) { h[i] = 0.f; g_c[i] = 0.f; }
    if (i < 17) g_cnt[i] = 0;
}

// ---------------------------------------------------------------------------
// Length sort (counting sort, descending length): hist -> scan -> scatter
// ---------------------------------------------------------------------------
__global__ void hist_kernel(const int* __restrict__ lens) {
    int i = blockIdx.x * blockDim.x + threadIdx.x;
    if (i < BT_) atomicAdd(&g_cnt[lens[i]], 1);
}
__global__ void scan_kernel() {
    if (threadIdx.x == 0) {
        int acc = 0;
        for (int l = 16; l >= 1; --l) { g_off[l] = acc; acc += g_cnt[l]; }
        g_Mt[0] = BT_;
        for (int t = 1; t <= 16; ++t) g_Mt[t] = g_off[t];  // desc_start[t] = #{len>t}
        g_Mt[17] = 0;
    }
}
__global__ void scatter_kernel(const int* __restrict__ lens) {
    int i = blockIdx.x * blockDim.x + threadIdx.x;
    if (i < BT_) {
        int pos = atomicAdd(&g_off[lens[i]], 1);
        g_perm[pos] = i;
    }
}

// ---------------------------------------------------------------------------
// W_hh split + gate permutation: row r (gate q=r>>9, unit u=r&511) -> 4u+q
// ---------------------------------------------------------------------------
__global__ void wsplit_kernel(const float* __restrict__ W) {
    int i = blockIdx.x * blockDim.x + threadIdx.x;
    if (i >= G4_ * H_) return;
    int r = i / H_, cc = i % H_;
    int pr = 4 * (r & 511) + (r >> 9);
    __nv_bfloat16 hi, lo;
    split_bf16(W[i], hi, lo);
    g_WB[(size_t)pr * (2 * H_) + cc]      = hi;
    g_WB[(size_t)pr * (2 * H_) + H_ + cc] = lo;
}

// ---------------------------------------------------------------------------
// XG[v][perm(n)] = emb[v]·W_ih[n] + b_ih[n] + b_hh[n]  (fp32 exact)
// ---------------------------------------------------------------------------
__global__ void xg_kernel(const float* __restrict__ emb,
                          const float* __restrict__ W_ih,
                          const float* __restrict__ b_ih,
                          const float* __restrict__ b_hh) {
    __shared__ float Es[16][16];
    __shared__ float Ws[16][17];
    int tx = threadIdx.x, ty = threadIdx.y;
    int n = blockIdx.x * 16 + tx;
    int v = blockIdx.y * 16 + ty;
    float acc = 0.f;
    for (int k0 = 0; k0 < E_; k0 += 16) {
        Es[ty][tx] = emb[v * E_ + k0 + tx];
        Ws[ty][tx] = W_ih[(blockIdx.x * 16 + ty) * E_ + k0 + tx];
        __syncthreads();
#pragma unroll
        for (int k = 0; k < 16; k++) acc += Es[ty][k] * Ws[tx][k];
        __syncthreads();
    }
    int pn = 4 * (n & 511) + (n >> 9);
    g_XG[v * G4_ + pn] = acc + b_ih[n] + b_hh[n];
}

// ---------------------------------------------------------------------------
// Fused step kernel (length-sorted row space):
//   bf16x3 wmma GEMM (128x128 tile, BK=64, 3-stage cp.async, 1 barrier/chunk)
//   + LSTM cell epilogue. CTAs with bm >= M_t exit immediately.
// SMEM (111616 B): [0,512) ids, [512,1024) perm, [1024,...) 3x36864 pipeline
//   (epilogue reuses pipeline region: 8 warps x 9216B staging [64][36] fp32)
// ---------------------------------------------------------------------------
#define LDMS  72        // smem row stride in bf16 elems (144B)
#define SM_IDS   0
#define SM_PERM  512
#define SM_PIPE  1024
#define STAGE_BYTES 36864
#define SMEM_TOTAL  111616

__global__ void __launch_bounds__(256, 2)
step_kernel(const int* __restrict__ seq, float* __restrict__ h, int t) {
    const int Mt = g_Mt[t];
    const int bm = blockIdx.y * 128;     // sorted-space rows
    if (bm >= Mt) return;                // whole CTA frozen
    extern __shared__ char smem[];
    const uint32_t sb = smem_u32(smem);
    const int tid = threadIdx.x;
    const int bn  = blockIdx.x * 128;    // permuted gate-column tile
    const int rd  = t & 1, wr = rd ^ 1;

    int* ids_s  = (int*)(smem + SM_IDS);
    int* perm_s = (int*)(smem + SM_PERM);
    if (tid < 128) {
        int orig = g_perm[bm + tid];
        perm_s[tid] = orig;
        ids_s[tid]  = seq[orig * L_ + t];
    }

    const __nv_bfloat16* __restrict__ hA = g_hA[rd];
    const int aoff[3] = {0, 0, H_};      // passes: hi*hi, hi*lo, lo*hi
    const int boff[3] = {0, H_, 0};

    // cp.async mapping: thread -> (row = tid>>1, 64B half = tid&1), 4x16B each
    const int row  = tid >> 1;
    const int half = tid & 1;
    const __nv_bfloat16* Agbase = hA   + (size_t)(bm + row) * (2 * H_) + half * 32;
    const __nv_bfloat16* Bgbase = g_WB + (size_t)(bn + row) * (2 * H_) + half * 32;
    const uint32_t AsmBase = sb + SM_PIPE + row * 144 + half * 64;
    const uint32_t BsmBase = AsmBase + 18432;

#define ISSUE_CHUNK(c, s) do {                                                  \
    int _p = (c) >> 3, _k0 = ((c) & 7) * 64;                                    \
    const __nv_bfloat16* _ag = Agbase + aoff[_p] + _k0;                         \
    const __nv_bfloat16* _bg = Bgbase + boff[_p] + _k0;                         \
    uint32_t _as = AsmBase + (s) * STAGE_BYTES;                                 \
    uint32_t _bs = BsmBase + (s) * STAGE_BYTES;                                 \
    _Pragma("unroll")                                                           \
    for (int _v = 0; _v < 4; _v++) {                                            \
        asm volatile("cp.async.cg.shared.global [%0], [%1], 16;"                \
                     :: "r"(_as + _v * 16), "l"(_ag + _v * 8) : "memory");      \
        asm volatile("cp.async.cg.shared.global [%0], [%1], 16;"                \
                     :: "r"(_bs + _v * 16), "l"(_bg + _v * 8) : "memory");      \
    }                                                                           \
    asm volatile("cp.async.commit_group;" ::: "memory");                        \
} while (0)

    const int w  = tid >> 5;
    const int wm = (w & 1) * 64;         // warp M offset
    const int wn = (w >> 1) * 32;        // warp N offset

    wmma::fragment<wmma::accumulator, 16, 16, 16, float> acc[4][2];
#pragma unroll
    for (int i = 0; i < 4; i++)
#pragma unroll
        for (int j = 0; j < 2; j++) wmma::fill_fragment(acc[i][j], 0.f);

    ISSUE_CHUNK(0, 0);
    ISSUE_CHUNK(1, 1);

    int st = 0;                          // stage of chunk c
#pragma unroll 1
    for (int c = 0; c < 24; c++) {       // 3 passes x 8 chunks (BK=64)
        if (c < 23) asm volatile("cp.async.wait_group 1;" ::: "memory");
        else        asm volatile("cp.async.wait_group 0;" ::: "memory");
        __syncthreads();                 // all warps done with stage (c-1)%3 too
        if (c + 2 < 24) {
            int sn = st + 2; if (sn >= 3) sn -= 3;
            ISSUE_CHUNK(c + 2, sn);
        }
        const __nv_bfloat16* As =
            (const __nv_bfloat16*)(smem + SM_PIPE + st * STAGE_BYTES);
        const __nv_bfloat16* Bs = As + 18432 / 2;   // bf16 elems
#pragma unroll
        for (int ks = 0; ks < 4; ks++) {
            wmma::fragment<wmma::matrix_a, 16, 16, 16, __nv_bfloat16, wmma::row_major> af[4];
            wmma::fragment<wmma::matrix_b, 16, 16, 16, __nv_bfloat16, wmma::col_major> bf[2];
#pragma unroll
            for (int i = 0; i < 4; i++)
                wmma::load_matrix_sync(af[i], As + (wm + i * 16) * LDMS + ks * 16, LDMS);
#pragma unroll
            for (int j = 0; j < 2; j++)
                wmma::load_matrix_sync(bf[j], Bs + (wn + j * 16) * LDMS + ks * 16, LDMS);
#pragma unroll
            for (int i = 0; i < 4; i++)
#pragma unroll
                for (int j = 0; j < 2; j++)
                    wmma::mma_sync(acc[i][j], af[i], bf[j], acc[i][j]);
        }
        if (++st == 3) st = 0;
    }
#undef ISSUE_CHUNK
    __syncthreads();                     // pipeline smem -> staging reuse

    // ---- Epilogue: stage warp tile to smem, then LSTM cell ------------------
    float* stg = (float*)(smem + SM_PIPE + w * 9216);   // [64][36] fp32
#pragma unroll
    for (int i = 0; i < 4; i++)
#pragma unroll
        for (int j = 0; j < 2; j++)
            wmma::store_matrix_sync(stg + (i * 16) * 36 + j * 16, acc[i][j],
                                    36, wmma::mem_row_major);
    __syncwarp();

    const int lane  = tid & 31;
    const int u_loc = lane & 7;              // unit within warp's 8 units
    const int r0    = (lane >> 3) * 16;      // 16-row slab per lane
    const int hcol  = ((bn + wn) >> 2) + u_loc;
    __nv_bfloat16* haw = g_hA[wr];

#pragma unroll 1
    for (int rr = 0; rr < 16; rr++) {
        const int r    = r0 + rr;            // row in warp tile
        const int mrow = wm + r;             // row in CTA tile
        const int ms   = bm + mrow;          // sorted row index
        if (ms >= Mt) continue;              // frozen: untouched, never read again
        float4 g4 = *(float4*)(stg + r * 36 + u_loc * 4);
        const float* xr = g_XG + (size_t)ids_s[mrow] * G4_ + bn + wn + u_loc * 4;
        float4 x4 = *(const float4*)xr;
        float iv = sigmoidf_(g4.x + x4.x);
        float fv = sigmoidf_(g4.y + x4.y);
        float gv = tanhf(    g4.z + x4.z);
        float ov = sigmoidf_(g4.w + x4.w);
        const int ci = ms * H_ + hcol;       // c lives in sorted space
        float cn = fv * g_c[ci] + iv * gv;
        g_c[ci] = cn;
        float hn = ov * tanhf(cn);
        h[perm_s[mrow] * H_ + hcol] = hn;    // output in original space
        __nv_bfloat16 hi, lo;
        split_bf16(hn, hi, lo);
        const size_t hb = (size_t)ms * (2 * H_) + hcol;
        haw[hb]      = hi;
        haw[hb + H_] = lo;
    }
}

// ---------------------------------------------------------------------------
// Launch
// ---------------------------------------------------------------------------
extern "C" void kernel_launch(void* const* d_in, const int* in_sizes, int n_in,
                              void* d_out, int out_size) {
    const int*   seq  = (const int*)d_in[0];     // [32,128,16] int32
    const int*   lens = (const int*)d_in[1];     // [32,128]    int32
    const float* emb  = (const float*)d_in[2];   // [256,256]
    const float* W_ih = (const float*)d_in[3];   // [2048,256]
    const float* W_hh = (const float*)d_in[4];   // [2048,512]
    const float* b_ih = (const float*)d_in[5];   // [2048]
    const float* b_hh = (const float*)d_in[6];   // [2048]
    float* h = (float*)d_out;                    // [4096,512]

    cudaFuncSetAttribute(step_kernel, cudaFuncAttributeMaxDynamicSharedMemorySize,
                         SMEM_TOTAL);

    init_kernel<<<(2 * BT_ * H_ + 255) / 256, 256>>>(h);
    hist_kernel<<<(BT_ + 255) / 256, 256>>>(lens);
    scan_kernel<<<1, 32>>>();
    scatter_kernel<<<(BT_ + 255) / 256, 256>>>(lens);
    wsplit_kernel<<<(G4_ * H_ + 255) / 256, 256>>>(W_hh);
    xg_kernel<<<dim3(G4_ / 16, VOC_ / 16), dim3(16, 16)>>>(emb, W_ih, b_ih, b_hh);

    dim3 ggrid(G4_ / 128, BT_ / 128);            // (16, 32); frozen CTAs early-exit
    for (int t = 0; t < L_; t++)
        step_kernel<<<ggrid, 256, SMEM_TOTAL>>>(seq, h, t);
}